// round 14
// baseline (speedup 1.0000x reference)
#include <cuda_runtime.h>
#include <cuda_fp16.h>
#include <stdint.h>

// out[num_rows, 128] = segment_sum(W[cols]*vals, rows) + b
//
// R13: base = R11 (82.4us best; R12's self-reset reverted). One mechanism:
// row_gather is now PERSISTENT (grid = 148*8 blocks, warp grid-stride over
// rows) with next-row metadata prefetch: while row r is processed, the
// cnt + slot loads for row r+nwarps are already in flight. Inner FFMA2
// loop byte-identical to R11. Bias/ovf_n hoisted to once per warp
// (row-independent). zero_kernel = full R11 version.

static constexpr int UNITS    = 128;
static constexpr int WCOLS    = 8192;
static constexpr int SLOTS    = 48;
static constexpr int MAX_ROWS = 1 << 17;
static constexpr int OVF_CAP  = 65536;

__device__ __align__(16) __half g_Wh[WCOLS * UNITS];  // 2 MB fp16 W
__device__ int    g_cnt[MAX_ROWS];
__device__ float2 g_slot[(size_t)MAX_ROWS * SLOTS];   // (val, bitcast(col))
__device__ float4 g_ovf[OVF_CAP];                     // (val, col, row, -)
__device__ int    g_ovf_n;

__device__ __forceinline__ unsigned long long h2_to_f32x2(uint32_t h2) {
    unsigned long long w;
    asm("{\n\t"
        ".reg .f16 h0, h1;\n\t"
        ".reg .f32 f0, f1;\n\t"
        "mov.b32 {h0, h1}, %1;\n\t"
        "cvt.f32.f16 f0, h0;\n\t"
        "cvt.f32.f16 f1, h1;\n\t"
        "mov.b64 %0, {f0, f1};\n\t"
        "}" : "=l"(w) : "r"(h2));
    return w;
}

__device__ __forceinline__ unsigned long long dup_f32x2(float v) {
    unsigned long long w;
    asm("mov.b64 %0, {%1, %1};" : "=l"(w) : "f"(v));
    return w;
}

__device__ __forceinline__ void ffma2(unsigned long long& acc,
                                      unsigned long long a,
                                      unsigned long long b) {
    asm("fma.rn.f32x2 %0, %1, %2, %0;" : "+l"(acc) : "l"(a), "l"(b));
}

__device__ __forceinline__ float2 unpack_f32x2(unsigned long long w) {
    float lo, hi;
    asm("mov.b64 {%0, %1}, %2;" : "=f"(lo), "=f"(hi) : "l"(w));
    return make_float2(lo, hi);
}

// ---- k0: zero per-row counters + overflow counter ----
__global__ void zero_kernel(int num_rows) {
    int i = blockIdx.x * blockDim.x + threadIdx.x;
    if (i < num_rows) g_cnt[i] = 0;
    if (i == 0) g_ovf_n = 0;
}

__device__ __forceinline__ void bin_one(float v, int r, int c) {
    int pos = atomicAdd(&g_cnt[r], 1);
    if (pos < SLOTS) {
        g_slot[(size_t)r * SLOTS + pos] = make_float2(v, __int_as_float(c));
    } else {
        int op = atomicAdd(&g_ovf_n, 1);
        if (op < OVF_CAP)
            g_ovf[op] = make_float4(v, __int_as_float(c), __int_as_float(r), 0.f);
    }
}

// ---- k1: scatter nonzeros into per-row slots (2/thread) + convert W ----
__global__ void scatter_convert_kernel(const float* __restrict__ vals,
                                       const int* __restrict__ rows,
                                       const int* __restrict__ cols,
                                       const float* __restrict__ W,
                                       int nnz, int n4) {
    int t = blockIdx.x * blockDim.x + threadIdx.x;

    if (t < n4) {  // W conversion rides along on the first 262144 threads
        float4 f = __ldg(reinterpret_cast<const float4*>(W) + t);
        __half2 h0 = __floats2half2_rn(f.x, f.y);
        __half2 h1 = __floats2half2_rn(f.z, f.w);
        uint2 u;
        u.x = *reinterpret_cast<uint32_t*>(&h0);
        u.y = *reinterpret_cast<uint32_t*>(&h1);
        reinterpret_cast<uint2*>(g_Wh)[t] = u;
    }

    int i0 = t * 2;
    if (i0 >= nnz) return;

    if (i0 + 2 <= nnz) {
        float2 v2 = __ldg(reinterpret_cast<const float2*>(vals + i0));
        int2   r2 = __ldg(reinterpret_cast<const int2*>(rows + i0));
        int2   c2 = __ldg(reinterpret_cast<const int2*>(cols + i0));
        int pos0 = atomicAdd(&g_cnt[r2.x], 1);
        int pos1 = atomicAdd(&g_cnt[r2.y], 1);
        if (pos0 < SLOTS) {
            g_slot[(size_t)r2.x * SLOTS + pos0] = make_float2(v2.x, __int_as_float(c2.x));
        } else {
            int op = atomicAdd(&g_ovf_n, 1);
            if (op < OVF_CAP)
                g_ovf[op] = make_float4(v2.x, __int_as_float(c2.x), __int_as_float(r2.x), 0.f);
        }
        if (pos1 < SLOTS) {
            g_slot[(size_t)r2.y * SLOTS + pos1] = make_float2(v2.y, __int_as_float(c2.y));
        } else {
            int op = atomicAdd(&g_ovf_n, 1);
            if (op < OVF_CAP)
                g_ovf[op] = make_float4(v2.y, __int_as_float(c2.y), __int_as_float(r2.y), 0.f);
        }
    } else {
        bin_one(vals[i0], rows[i0], cols[i0]);
    }
}

// ---- k2: persistent warps, grid-stride rows, next-row prefetch ----
__global__ void __launch_bounds__(256) row_gather_kernel(
        const float* __restrict__ b,
        float* __restrict__ out,
        int num_rows) {
    int nwarps = (gridDim.x * blockDim.x) >> 5;
    int gwarp  = (blockIdx.x * blockDim.x + threadIdx.x) >> 5;
    int lane   = threadIdx.x & 31;

    int hi  = lane >> 4;        // which nonzero of the pair this lane serves
    int sub = lane & 15;        // covers units [8*sub, 8*sub+8)
    int ubase = sub * 8 + hi * 4;

    // Per-warp invariants: one load each, entire kernel.
    float4 bias = __ldg(reinterpret_cast<const float4*>(b) + (ubase >> 2));
    int ovn = g_ovf_n;
    if (ovn > OVF_CAP) ovn = OVF_CAP;

    const char* Wl = reinterpret_cast<const char*>(g_Wh) + sub * 16;

    int row = gwarp;
    if (row >= num_rows) return;

    // Prologue for the first row.
    int   cnt_raw = g_cnt[row];
    float2 pre    = __ldg(g_slot + (size_t)row * SLOTS + lane);

    while (true) {
        // Prefetch next row's metadata before processing the current row.
        int nrow = row + nwarps;
        bool more = nrow < num_rows;
        int   ncnt = 0;
        float2 npre = make_float2(0.f, 0.f);
        if (more) {
            ncnt = g_cnt[nrow];
            npre = __ldg(g_slot + (size_t)nrow * SLOTS + lane);
        }

        const float2* slots = g_slot + (size_t)row * SLOTS;
        int cnt = cnt_raw > SLOTS ? SLOTS : cnt_raw;

        unsigned long long acc0 = 0, acc1 = 0, acc2 = 0, acc3 = 0;

        // Chunk 1 from the preloaded data (covers cnt <= 32: ~all rows).
        int m0 = cnt > 32 ? 32 : cnt;
        {
            float v = (lane < m0) ? pre.x : 0.f;
            int   c = (lane < m0) ? __float_as_int(pre.y) : 0;

            int iters = (m0 + 1) >> 1;
            #pragma unroll 8
            for (int p = 0; p < iters; ++p) {
                int j  = 2 * p + hi;
                float vj = __shfl_sync(0xffffffffu, v, j);   // 0 if j >= m0
                int   cj = __shfl_sync(0xffffffffu, c, j);

                uint4 u = __ldg(reinterpret_cast<const uint4*>(
                              Wl + ((size_t)(uint32_t)cj << 8)));
                unsigned long long vv = dup_f32x2(vj);
                ffma2(acc0, h2_to_f32x2(u.x), vv);
                ffma2(acc1, h2_to_f32x2(u.y), vv);
                ffma2(acc2, h2_to_f32x2(u.z), vv);
                ffma2(acc3, h2_to_f32x2(u.w), vv);
            }
        }

        // Rare chunk 2 (cnt > 32).
        if (cnt > 32) {
            int m = cnt - 32;
            float v = 0.f;
            int   c = 0;
            if (lane < m) {
                float2 p = __ldg(slots + 32 + lane);
                v = p.x;
                c = __float_as_int(p.y);
            }
            int iters = (m + 1) >> 1;
            for (int p = 0; p < iters; ++p) {
                int j  = 2 * p + hi;
                float vj = __shfl_sync(0xffffffffu, v, j);
                int   cj = __shfl_sync(0xffffffffu, c, j);

                uint4 u = __ldg(reinterpret_cast<const uint4*>(
                              Wl + ((size_t)(uint32_t)cj << 8)));
                unsigned long long vv = dup_f32x2(vj);
                ffma2(acc0, h2_to_f32x2(u.x), vv);
                ffma2(acc1, h2_to_f32x2(u.y), vv);
                ffma2(acc2, h2_to_f32x2(u.z), vv);
                ffma2(acc3, h2_to_f32x2(u.w), vv);
            }
        }

        // Epilogue: unpack, combine halves, overflow fixup, bias, store.
        float2 p0 = unpack_f32x2(acc0);
        float2 p1 = unpack_f32x2(acc1);
        float2 p2 = unpack_f32x2(acc2);
        float2 p3 = unpack_f32x2(acc3);
        float4 accA = make_float4(p0.x, p0.y, p1.x, p1.y);
        float4 accB = make_float4(p2.x, p2.y, p3.x, p3.y);

        accA.x += __shfl_xor_sync(0xffffffffu, accA.x, 16);
        accA.y += __shfl_xor_sync(0xffffffffu, accA.y, 16);
        accA.z += __shfl_xor_sync(0xffffffffu, accA.z, 16);
        accA.w += __shfl_xor_sync(0xffffffffu, accA.w, 16);
        accB.x += __shfl_xor_sync(0xffffffffu, accB.x, 16);
        accB.y += __shfl_xor_sync(0xffffffffu, accB.y, 16);
        accB.z += __shfl_xor_sync(0xffffffffu, accB.z, 16);
        accB.w += __shfl_xor_sync(0xffffffffu, accB.w, 16);

        float4 r = hi ? accB : accA;

        if (ovn > 0) {
            for (int e = 0; e < ovn; ++e) {
                float4 ent = g_ovf[e];
                if (__float_as_int(ent.z) == row) {
                    float ve = ent.x;
                    size_t ce = (size_t)(uint32_t)__float_as_int(ent.y);
                    uint2 u = __ldg(reinterpret_cast<const uint2*>(
                                  g_Wh + ce * UNITS + ubase));
                    float2 e0 = __half22float2(*reinterpret_cast<__half2*>(&u.x));
                    float2 e1 = __half22float2(*reinterpret_cast<__half2*>(&u.y));
                    r.x = fmaf(e0.x, ve, r.x);
                    r.y = fmaf(e0.y, ve, r.y);
                    r.z = fmaf(e1.x, ve, r.z);
                    r.w = fmaf(e1.y, ve, r.w);
                }
            }
        }

        r.x += bias.x; r.y += bias.y; r.z += bias.z; r.w += bias.w;
        *reinterpret_cast<float4*>(out + (size_t)row * UNITS + ubase) = r;

        if (!more) break;
        row     = nrow;
        cnt_raw = ncnt;
        pre     = npre;
    }
}

extern "C" void kernel_launch(void* const* d_in, const int* in_sizes, int n_in,
                              void* d_out, int out_size) {
    const float* vals = (const float*)d_in[0];
    const int*   rows = (const int*)d_in[1];
    const int*   cols = (const int*)d_in[2];
    const float* W    = (const float*)d_in[3];
    const float* b    = (const float*)d_in[4];
    float* out = (float*)d_out;

    int nnz = in_sizes[0];
    int num_rows = out_size / UNITS;

    const int T = 256;
    int n4 = WCOLS * UNITS / 4;             // 262144 float4s of W
    int nh = (nnz + 1) / 2;                 // threads for 2-wide scatter
    int work = nh > n4 ? nh : n4;

    zero_kernel<<<(num_rows + T - 1) / T, T>>>(num_rows);
    scatter_convert_kernel<<<(work + T - 1) / T, T>>>(vals, rows, cols, W, nnz, n4);
    // Persistent gather: ~one wave of blocks (148 SMs x 8 blocks).
    int gblocks = 148 * 8;
    row_gather_kernel<<<gblocks, T>>>(b, out, num_rows);
}

// round 15
// speedup vs baseline: 1.1583x; 1.1583x over previous
#include <cuda_runtime.h>
#include <cuda_fp16.h>
#include <stdint.h>

// out[num_rows, 128] = segment_sum(W[cols]*vals, rows) + b
//
// R14: base = R11 (82.4us best; R12/R13 restructures reverted). One change:
// slot metadata packed into ONE uint32 per nonzero: (col << 16) | fp16(val).
//   - gather inner loop: 1 shfl per pair instead of 2 (26-cyc SHFL off the
//     dependent chain), unpack = shift + cvt (4-cyc pipes)
//   - slot traffic halves (8B -> 4B per nnz)
// val fp16 adds ~2^-11 independent rel-err: total ~2.8e-4, under 1e-3.
// Everything else identical to R11.

static constexpr int UNITS    = 128;
static constexpr int WCOLS    = 8192;
static constexpr int SLOTS    = 48;
static constexpr int MAX_ROWS = 1 << 17;
static constexpr int OVF_CAP  = 65536;

__device__ __align__(16) __half g_Wh[WCOLS * UNITS];   // 2 MB fp16 W
__device__ int      g_cnt[MAX_ROWS];
__device__ uint32_t g_slot[(size_t)MAX_ROWS * SLOTS];  // (col<<16)|fp16(val)
__device__ float4   g_ovf[OVF_CAP];                    // (val, col, row, -)
__device__ int      g_ovf_n;

__device__ __forceinline__ unsigned long long h2_to_f32x2(uint32_t h2) {
    unsigned long long w;
    asm("{\n\t"
        ".reg .f16 h0, h1;\n\t"
        ".reg .f32 f0, f1;\n\t"
        "mov.b32 {h0, h1}, %1;\n\t"
        "cvt.f32.f16 f0, h0;\n\t"
        "cvt.f32.f16 f1, h1;\n\t"
        "mov.b64 %0, {f0, f1};\n\t"
        "}" : "=l"(w) : "r"(h2));
    return w;
}

__device__ __forceinline__ unsigned long long dup_f32x2(float v) {
    unsigned long long w;
    asm("mov.b64 %0, {%1, %1};" : "=l"(w) : "f"(v));
    return w;
}

__device__ __forceinline__ void ffma2(unsigned long long& acc,
                                      unsigned long long a,
                                      unsigned long long b) {
    asm("fma.rn.f32x2 %0, %1, %2, %0;" : "+l"(acc) : "l"(a), "l"(b));
}

__device__ __forceinline__ float2 unpack_f32x2(unsigned long long w) {
    float lo, hi;
    asm("mov.b64 {%0, %1}, %2;" : "=f"(lo), "=f"(hi) : "l"(w));
    return make_float2(lo, hi);
}

__device__ __forceinline__ uint32_t pack_slot(float v, int c) {
    return ((uint32_t)c << 16) |
           (uint32_t)__half_as_ushort(__float2half_rn(v));
}

// low 16 bits -> f32 value
__device__ __forceinline__ float slot_val(uint32_t p) {
    float f;
    asm("{\n\t"
        ".reg .b16 lo, hi;\n\t"
        "mov.b32 {lo, hi}, %1;\n\t"
        "cvt.f32.f16 %0, lo;\n\t"
        "}" : "=f"(f) : "r"(p));
    return f;
}

// ---- k0: zero per-row counters + overflow counter ----
__global__ void zero_kernel(int num_rows) {
    int i = blockIdx.x * blockDim.x + threadIdx.x;
    if (i < num_rows) g_cnt[i] = 0;
    if (i == 0) g_ovf_n = 0;
}

__device__ __forceinline__ void bin_one(float v, int r, int c) {
    int pos = atomicAdd(&g_cnt[r], 1);
    if (pos < SLOTS) {
        g_slot[(size_t)r * SLOTS + pos] = pack_slot(v, c);
    } else {
        int op = atomicAdd(&g_ovf_n, 1);
        if (op < OVF_CAP)
            g_ovf[op] = make_float4(v, __int_as_float(c), __int_as_float(r), 0.f);
    }
}

// ---- k1: scatter nonzeros into per-row slots (2/thread) + convert W ----
__global__ void scatter_convert_kernel(const float* __restrict__ vals,
                                       const int* __restrict__ rows,
                                       const int* __restrict__ cols,
                                       const float* __restrict__ W,
                                       int nnz, int n4) {
    int t = blockIdx.x * blockDim.x + threadIdx.x;

    if (t < n4) {  // W conversion rides along on the first 262144 threads
        float4 f = __ldg(reinterpret_cast<const float4*>(W) + t);
        __half2 h0 = __floats2half2_rn(f.x, f.y);
        __half2 h1 = __floats2half2_rn(f.z, f.w);
        uint2 u;
        u.x = *reinterpret_cast<uint32_t*>(&h0);
        u.y = *reinterpret_cast<uint32_t*>(&h1);
        reinterpret_cast<uint2*>(g_Wh)[t] = u;
    }

    int i0 = t * 2;
    if (i0 >= nnz) return;

    if (i0 + 2 <= nnz) {
        float2 v2 = __ldg(reinterpret_cast<const float2*>(vals + i0));
        int2   r2 = __ldg(reinterpret_cast<const int2*>(rows + i0));
        int2   c2 = __ldg(reinterpret_cast<const int2*>(cols + i0));
        int pos0 = atomicAdd(&g_cnt[r2.x], 1);
        int pos1 = atomicAdd(&g_cnt[r2.y], 1);
        if (pos0 < SLOTS) {
            g_slot[(size_t)r2.x * SLOTS + pos0] = pack_slot(v2.x, c2.x);
        } else {
            int op = atomicAdd(&g_ovf_n, 1);
            if (op < OVF_CAP)
                g_ovf[op] = make_float4(v2.x, __int_as_float(c2.x), __int_as_float(r2.x), 0.f);
        }
        if (pos1 < SLOTS) {
            g_slot[(size_t)r2.y * SLOTS + pos1] = pack_slot(v2.y, c2.y);
        } else {
            int op = atomicAdd(&g_ovf_n, 1);
            if (op < OVF_CAP)
                g_ovf[op] = make_float4(v2.y, __int_as_float(c2.y), __int_as_float(r2.y), 0.f);
        }
    } else {
        bin_one(vals[i0], rows[i0], cols[i0]);
    }
}

// ---- k2: warp per row; half-warp split; FFMA2; parallel prologue ----
__global__ void __launch_bounds__(256) row_gather_kernel(
        const float* __restrict__ b,
        float* __restrict__ out,
        int num_rows) {
    int warp = (blockIdx.x * blockDim.x + threadIdx.x) >> 5;
    int lane = threadIdx.x & 31;
    if (warp >= num_rows) return;

    int hi  = lane >> 4;        // which nonzero of the pair this lane serves
    int sub = lane & 15;        // covers units [8*sub, 8*sub+8)

    const uint32_t* slots = g_slot + (size_t)warp * SLOTS;

    // Parallel prologue: count + first slot chunk are independent loads,
    // both issued before either resolves (lane < 32 <= SLOTS: in-bounds).
    int cnt_raw = g_cnt[warp];
    uint32_t pre = __ldg(slots + lane);

    int cnt = cnt_raw > SLOTS ? SLOTS : cnt_raw;

    const char* Wl = reinterpret_cast<const char*>(g_Wh) + sub * 16;

    unsigned long long acc0 = 0, acc1 = 0, acc2 = 0, acc3 = 0;

    // Chunk 1 from the preloaded data (covers cnt <= 32: ~all rows).
    int m0 = cnt > 32 ? 32 : cnt;
    {
        uint32_t pk = (lane < m0) ? pre : 0u;   // fp16(0)=0, col 0: safe

        int iters = (m0 + 1) >> 1;
        #pragma unroll 8
        for (int p = 0; p < iters; ++p) {
            int j  = 2 * p + hi;
            uint32_t pj = __shfl_sync(0xffffffffu, pk, j);  // ONE shfl
            float vj = slot_val(pj);
            uint32_t cj = pj >> 16;

            uint4 u = __ldg(reinterpret_cast<const uint4*>(
                          Wl + ((size_t)cj << 8)));
            unsigned long long vv = dup_f32x2(vj);
            ffma2(acc0, h2_to_f32x2(u.x), vv);
            ffma2(acc1, h2_to_f32x2(u.y), vv);
            ffma2(acc2, h2_to_f32x2(u.z), vv);
            ffma2(acc3, h2_to_f32x2(u.w), vv);
        }
    }

    // Rare chunk 2 (cnt > 32): conditional load as before.
    if (cnt > 32) {
        int m = cnt - 32;
        uint32_t pk = 0u;
        if (lane < m) pk = __ldg(slots + 32 + lane);
        int iters = (m + 1) >> 1;
        for (int p = 0; p < iters; ++p) {
            int j  = 2 * p + hi;
            uint32_t pj = __shfl_sync(0xffffffffu, pk, j);
            float vj = slot_val(pj);
            uint32_t cj = pj >> 16;

            uint4 u = __ldg(reinterpret_cast<const uint4*>(
                          Wl + ((size_t)cj << 8)));
            unsigned long long vv = dup_f32x2(vj);
            ffma2(acc0, h2_to_f32x2(u.x), vv);
            ffma2(acc1, h2_to_f32x2(u.y), vv);
            ffma2(acc2, h2_to_f32x2(u.z), vv);
            ffma2(acc3, h2_to_f32x2(u.w), vv);
        }
    }

    // Unpack to scalars, then combine even/odd half-warp partials.
    float2 p0 = unpack_f32x2(acc0);
    float2 p1 = unpack_f32x2(acc1);
    float2 p2 = unpack_f32x2(acc2);
    float2 p3 = unpack_f32x2(acc3);
    float4 accA = make_float4(p0.x, p0.y, p1.x, p1.y);  // units [8s, 8s+4)
    float4 accB = make_float4(p2.x, p2.y, p3.x, p3.y);  // units [8s+4, 8s+8)

    accA.x += __shfl_xor_sync(0xffffffffu, accA.x, 16);
    accA.y += __shfl_xor_sync(0xffffffffu, accA.y, 16);
    accA.z += __shfl_xor_sync(0xffffffffu, accA.z, 16);
    accA.w += __shfl_xor_sync(0xffffffffu, accA.w, 16);
    accB.x += __shfl_xor_sync(0xffffffffu, accB.x, 16);
    accB.y += __shfl_xor_sync(0xffffffffu, accB.y, 16);
    accB.z += __shfl_xor_sync(0xffffffffu, accB.z, 16);
    accB.w += __shfl_xor_sync(0xffffffffu, accB.w, 16);

    int ubase = sub * 8 + hi * 4;
    float4 r = hi ? accB : accA;

    // Inline overflow fixup (expected empty).
    int ovn = g_ovf_n;
    if (ovn > 0) {
        if (ovn > OVF_CAP) ovn = OVF_CAP;
        for (int e = 0; e < ovn; ++e) {
            float4 ent = g_ovf[e];
            if (__float_as_int(ent.z) == warp) {
                float ve = ent.x;
                size_t ce = (size_t)(uint32_t)__float_as_int(ent.y);
                uint2 u = __ldg(reinterpret_cast<const uint2*>(
                              g_Wh + ce * UNITS + ubase));
                float2 e0 = __half22float2(*reinterpret_cast<__half2*>(&u.x));
                float2 e1 = __half22float2(*reinterpret_cast<__half2*>(&u.y));
                r.x = fmaf(e0.x, ve, r.x);
                r.y = fmaf(e0.y, ve, r.y);
                r.z = fmaf(e1.x, ve, r.z);
                r.w = fmaf(e1.y, ve, r.w);
            }
        }
    }

    float4 bias = __ldg(reinterpret_cast<const float4*>(b) + (ubase >> 2));
    r.x += bias.x; r.y += bias.y; r.z += bias.z; r.w += bias.w;
    *reinterpret_cast<float4*>(out + (size_t)warp * UNITS + ubase) = r;
}

extern "C" void kernel_launch(void* const* d_in, const int* in_sizes, int n_in,
                              void* d_out, int out_size) {
    const float* vals = (const float*)d_in[0];
    const int*   rows = (const int*)d_in[1];
    const int*   cols = (const int*)d_in[2];
    const float* W    = (const float*)d_in[3];
    const float* b    = (const float*)d_in[4];
    float* out = (float*)d_out;

    int nnz = in_sizes[0];
    int num_rows = out_size / UNITS;

    const int T = 256;
    int n4 = WCOLS * UNITS / 4;             // 262144 float4s of W
    int nh = (nnz + 1) / 2;                 // threads for 2-wide scatter
    int work = nh > n4 ? nh : n4;

    zero_kernel<<<(num_rows + T - 1) / T, T>>>(num_rows);
    scatter_convert_kernel<<<(work + T - 1) / T, T>>>(vals, rows, cols, W, nnz, n4);
    int gblocks = (int)(((long)num_rows * 32 + T - 1) / T);
    row_gather_kernel<<<gblocks, T>>>(b, out, num_rows);
}

// round 16
// speedup vs baseline: 1.1625x; 1.0036x over previous
#include <cuda_runtime.h>
#include <cuda_fp16.h>
#include <stdint.h>

// out[num_rows, 128] = segment_sum(W[cols]*vals, rows) + b
//
// R15: base = R14 (80.64us best). One additive change: W fp32->fp16
// conversion moves from the (atomic-bound) scatter kernel into the
// (launch-bound, underutilized) prep kernel alongside counter zeroing.
// Scatter is now pure binning. Gather byte-identical to R14.

static constexpr int UNITS    = 128;
static constexpr int WCOLS    = 8192;
static constexpr int SLOTS    = 48;
static constexpr int MAX_ROWS = 1 << 17;
static constexpr int OVF_CAP  = 65536;

__device__ __align__(16) __half g_Wh[WCOLS * UNITS];   // 2 MB fp16 W
__device__ int      g_cnt[MAX_ROWS];
__device__ uint32_t g_slot[(size_t)MAX_ROWS * SLOTS];  // (col<<16)|fp16(val)
__device__ float4   g_ovf[OVF_CAP];                    // (val, col, row, -)
__device__ int      g_ovf_n;

__device__ __forceinline__ unsigned long long h2_to_f32x2(uint32_t h2) {
    unsigned long long w;
    asm("{\n\t"
        ".reg .f16 h0, h1;\n\t"
        ".reg .f32 f0, f1;\n\t"
        "mov.b32 {h0, h1}, %1;\n\t"
        "cvt.f32.f16 f0, h0;\n\t"
        "cvt.f32.f16 f1, h1;\n\t"
        "mov.b64 %0, {f0, f1};\n\t"
        "}" : "=l"(w) : "r"(h2));
    return w;
}

__device__ __forceinline__ unsigned long long dup_f32x2(float v) {
    unsigned long long w;
    asm("mov.b64 %0, {%1, %1};" : "=l"(w) : "f"(v));
    return w;
}

__device__ __forceinline__ void ffma2(unsigned long long& acc,
                                      unsigned long long a,
                                      unsigned long long b) {
    asm("fma.rn.f32x2 %0, %1, %2, %0;" : "+l"(acc) : "l"(a), "l"(b));
}

__device__ __forceinline__ float2 unpack_f32x2(unsigned long long w) {
    float lo, hi;
    asm("mov.b64 {%0, %1}, %2;" : "=f"(lo), "=f"(hi) : "l"(w));
    return make_float2(lo, hi);
}

__device__ __forceinline__ uint32_t pack_slot(float v, int c) {
    return ((uint32_t)c << 16) |
           (uint32_t)__half_as_ushort(__float2half_rn(v));
}

// low 16 bits -> f32 value
__device__ __forceinline__ float slot_val(uint32_t p) {
    float f;
    asm("{\n\t"
        ".reg .b16 lo, hi;\n\t"
        "mov.b32 {lo, hi}, %1;\n\t"
        "cvt.f32.f16 %0, lo;\n\t"
        "}" : "=f"(f) : "r"(p));
    return f;
}

// ---- k0: zero counters + convert W -> fp16 (independent prologue work) ----
__global__ void prep_kernel(const float* __restrict__ W, int n4, int num_rows) {
    int i = blockIdx.x * blockDim.x + threadIdx.x;
    if (i < num_rows) g_cnt[i] = 0;
    if (i == 0) g_ovf_n = 0;
    if (i < n4) {
        float4 f = __ldg(reinterpret_cast<const float4*>(W) + i);
        __half2 h0 = __floats2half2_rn(f.x, f.y);
        __half2 h1 = __floats2half2_rn(f.z, f.w);
        uint2 u;
        u.x = *reinterpret_cast<uint32_t*>(&h0);
        u.y = *reinterpret_cast<uint32_t*>(&h1);
        reinterpret_cast<uint2*>(g_Wh)[i] = u;
    }
}

__device__ __forceinline__ void bin_one(float v, int r, int c) {
    int pos = atomicAdd(&g_cnt[r], 1);
    if (pos < SLOTS) {
        g_slot[(size_t)r * SLOTS + pos] = pack_slot(v, c);
    } else {
        int op = atomicAdd(&g_ovf_n, 1);
        if (op < OVF_CAP)
            g_ovf[op] = make_float4(v, __int_as_float(c), __int_as_float(r), 0.f);
    }
}

// ---- k1: pure scatter: nonzeros into per-row slots (2/thread) ----
__global__ void scatter_kernel(const float* __restrict__ vals,
                               const int* __restrict__ rows,
                               const int* __restrict__ cols,
                               int nnz) {
    int t = blockIdx.x * blockDim.x + threadIdx.x;
    int i0 = t * 2;
    if (i0 >= nnz) return;

    if (i0 + 2 <= nnz) {
        float2 v2 = __ldg(reinterpret_cast<const float2*>(vals + i0));
        int2   r2 = __ldg(reinterpret_cast<const int2*>(rows + i0));
        int2   c2 = __ldg(reinterpret_cast<const int2*>(cols + i0));
        int pos0 = atomicAdd(&g_cnt[r2.x], 1);
        int pos1 = atomicAdd(&g_cnt[r2.y], 1);
        if (pos0 < SLOTS) {
            g_slot[(size_t)r2.x * SLOTS + pos0] = pack_slot(v2.x, c2.x);
        } else {
            int op = atomicAdd(&g_ovf_n, 1);
            if (op < OVF_CAP)
                g_ovf[op] = make_float4(v2.x, __int_as_float(c2.x), __int_as_float(r2.x), 0.f);
        }
        if (pos1 < SLOTS) {
            g_slot[(size_t)r2.y * SLOTS + pos1] = pack_slot(v2.y, c2.y);
        } else {
            int op = atomicAdd(&g_ovf_n, 1);
            if (op < OVF_CAP)
                g_ovf[op] = make_float4(v2.y, __int_as_float(c2.y), __int_as_float(r2.y), 0.f);
        }
    } else {
        bin_one(vals[i0], rows[i0], cols[i0]);
    }
}

// ---- k2: warp per row; half-warp split; FFMA2; parallel prologue ----
__global__ void __launch_bounds__(256) row_gather_kernel(
        const float* __restrict__ b,
        float* __restrict__ out,
        int num_rows) {
    int warp = (blockIdx.x * blockDim.x + threadIdx.x) >> 5;
    int lane = threadIdx.x & 31;
    if (warp >= num_rows) return;

    int hi  = lane >> 4;        // which nonzero of the pair this lane serves
    int sub = lane & 15;        // covers units [8*sub, 8*sub+8)

    const uint32_t* slots = g_slot + (size_t)warp * SLOTS;

    // Parallel prologue: count + first slot chunk are independent loads.
    int cnt_raw = g_cnt[warp];
    uint32_t pre = __ldg(slots + lane);

    int cnt = cnt_raw > SLOTS ? SLOTS : cnt_raw;

    const char* Wl = reinterpret_cast<const char*>(g_Wh) + sub * 16;

    unsigned long long acc0 = 0, acc1 = 0, acc2 = 0, acc3 = 0;

    // Chunk 1 from the preloaded data (covers cnt <= 32: ~all rows).
    int m0 = cnt > 32 ? 32 : cnt;
    {
        uint32_t pk = (lane < m0) ? pre : 0u;   // fp16(0)=0, col 0: safe

        int iters = (m0 + 1) >> 1;
        #pragma unroll 8
        for (int p = 0; p < iters; ++p) {
            int j  = 2 * p + hi;
            uint32_t pj = __shfl_sync(0xffffffffu, pk, j);  // ONE shfl
            float vj = slot_val(pj);
            uint32_t cj = pj >> 16;

            uint4 u = __ldg(reinterpret_cast<const uint4*>(
                          Wl + ((size_t)cj << 8)));
            unsigned long long vv = dup_f32x2(vj);
            ffma2(acc0, h2_to_f32x2(u.x), vv);
            ffma2(acc1, h2_to_f32x2(u.y), vv);
            ffma2(acc2, h2_to_f32x2(u.z), vv);
            ffma2(acc3, h2_to_f32x2(u.w), vv);
        }
    }

    // Rare chunk 2 (cnt > 32): conditional load as before.
    if (cnt > 32) {
        int m = cnt - 32;
        uint32_t pk = 0u;
        if (lane < m) pk = __ldg(slots + 32 + lane);
        int iters = (m + 1) >> 1;
        for (int p = 0; p < iters; ++p) {
            int j  = 2 * p + hi;
            uint32_t pj = __shfl_sync(0xffffffffu, pk, j);
            float vj = slot_val(pj);
            uint32_t cj = pj >> 16;

            uint4 u = __ldg(reinterpret_cast<const uint4*>(
                          Wl + ((size_t)cj << 8)));
            unsigned long long vv = dup_f32x2(vj);
            ffma2(acc0, h2_to_f32x2(u.x), vv);
            ffma2(acc1, h2_to_f32x2(u.y), vv);
            ffma2(acc2, h2_to_f32x2(u.z), vv);
            ffma2(acc3, h2_to_f32x2(u.w), vv);
        }
    }

    // Unpack to scalars, then combine even/odd half-warp partials.
    float2 p0 = unpack_f32x2(acc0);
    float2 p1 = unpack_f32x2(acc1);
    float2 p2 = unpack_f32x2(acc2);
    float2 p3 = unpack_f32x2(acc3);
    float4 accA = make_float4(p0.x, p0.y, p1.x, p1.y);  // units [8s, 8s+4)
    float4 accB = make_float4(p2.x, p2.y, p3.x, p3.y);  // units [8s+4, 8s+8)

    accA.x += __shfl_xor_sync(0xffffffffu, accA.x, 16);
    accA.y += __shfl_xor_sync(0xffffffffu, accA.y, 16);
    accA.z += __shfl_xor_sync(0xffffffffu, accA.z, 16);
    accA.w += __shfl_xor_sync(0xffffffffu, accA.w, 16);
    accB.x += __shfl_xor_sync(0xffffffffu, accB.x, 16);
    accB.y += __shfl_xor_sync(0xffffffffu, accB.y, 16);
    accB.z += __shfl_xor_sync(0xffffffffu, accB.z, 16);
    accB.w += __shfl_xor_sync(0xffffffffu, accB.w, 16);

    int ubase = sub * 8 + hi * 4;
    float4 r = hi ? accB : accA;

    // Inline overflow fixup (expected empty).
    int ovn = g_ovf_n;
    if (ovn > 0) {
        if (ovn > OVF_CAP) ovn = OVF_CAP;
        for (int e = 0; e < ovn; ++e) {
            float4 ent = g_ovf[e];
            if (__float_as_int(ent.z) == warp) {
                float ve = ent.x;
                size_t ce = (size_t)(uint32_t)__float_as_int(ent.y);
                uint2 u = __ldg(reinterpret_cast<const uint2*>(
                              g_Wh + ce * UNITS + ubase));
                float2 e0 = __half22float2(*reinterpret_cast<__half2*>(&u.x));
                float2 e1 = __half22float2(*reinterpret_cast<__half2*>(&u.y));
                r.x = fmaf(e0.x, ve, r.x);
                r.y = fmaf(e0.y, ve, r.y);
                r.z = fmaf(e1.x, ve, r.z);
                r.w = fmaf(e1.y, ve, r.w);
            }
        }
    }

    float4 bias = __ldg(reinterpret_cast<const float4*>(b) + (ubase >> 2));
    r.x += bias.x; r.y += bias.y; r.z += bias.z; r.w += bias.w;
    *reinterpret_cast<float4*>(out + (size_t)warp * UNITS + ubase) = r;
}

extern "C" void kernel_launch(void* const* d_in, const int* in_sizes, int n_in,
                              void* d_out, int out_size) {
    const float* vals = (const float*)d_in[0];
    const int*   rows = (const int*)d_in[1];
    const int*   cols = (const int*)d_in[2];
    const float* W    = (const float*)d_in[3];
    const float* b    = (const float*)d_in[4];
    float* out = (float*)d_out;

    int nnz = in_sizes[0];
    int num_rows = out_size / UNITS;

    const int T = 256;
    int n4 = WCOLS * UNITS / 4;             // 262144 float4s of W
    int pwork = n4 > num_rows ? n4 : num_rows;

    prep_kernel<<<(pwork + T - 1) / T, T>>>(W, n4, num_rows);
    int nh = (nnz + 1) / 2;                 // threads for 2-wide scatter
    scatter_kernel<<<(nh + T - 1) / T, T>>>(vals, rows, cols, nnz);
    int gblocks = (int)(((long)num_rows * 32 + T - 1) / T);
    row_gather_kernel<<<gblocks, T>>>(b, out, num_rows);
}